// round 1
// baseline (speedup 1.0000x reference)
#include <cuda_runtime.h>
#include <cuda_bf16.h>

#define Hh 100
#define Ww 136
#define HW (Hh*Ww)      // 13600
#define OH 200
#define OW 272
#define OHW (OH*OW)     // 54400
#define NPARAM 169

// params layout: w0[8][10]@0, w1[8][8]@80, w2[8]@144, b0[8]@152, b1[8]@160, b2@168

__global__ void dmh_zero(float* out) { out[0] = 0.0f; }

__global__ void __launch_bounds__(256)
dmh_kernel(const float* __restrict__ mask_feats,
           const float* __restrict__ params,
           const float* __restrict__ locs,
           const float* __restrict__ gt,
           const int*   __restrict__ im_inds,
           const int*   __restrict__ fpn_levels,
           float* __restrict__ out,
           float inv_n)
{
    extern __shared__ float smem[];
    float* Ls  = smem;              // HW logits
    float* Wp  = smem + HW;         // 169 params
    float* red = Wp + NPARAM + 7;   // 24 floats reduction scratch

    const int inst = blockIdx.x;
    const int tid  = threadIdx.x;

    // ---- Phase A: load per-instance params ----
    for (int i = tid; i < NPARAM; i += blockDim.x)
        Wp[i] = params[inst * NPARAM + i];

    const int im  = im_inds[inst];
    const int lvl = fpn_levels[inst];
    const float soi_tab[5] = {8.f, 16.f, 32.f, 64.f, 128.f};
    const float inv_soi = 1.0f / soi_tab[lvl];
    const float lx = locs[inst * 2 + 0];
    const float ly = locs[inst * 2 + 1];
    const float* __restrict__ feat = mask_feats + (size_t)im * 8 * HW;
    __syncthreads();

    // ---- Phase B: per-pixel 3-layer MLP -> logits in smem ----
    // register-block 4 consecutive pixels per thread
    for (int p0 = tid * 4; p0 < HW; p0 += blockDim.x * 4) {
        float v[10][4];
        #pragma unroll
        for (int j = 0; j < 4; j++) {
            int p = p0 + j;
            int y = p / Ww;
            int x = p - y * Ww;
            v[0][j] = (lx - (float)(x * 8 + 4)) * inv_soi;
            v[1][j] = (ly - (float)(y * 8 + 4)) * inv_soi;
        }
        #pragma unroll
        for (int c = 0; c < 8; c++) {
            float4 f = *reinterpret_cast<const float4*>(feat + c * HW + p0);
            v[2 + c][0] = f.x; v[2 + c][1] = f.y; v[2 + c][2] = f.z; v[2 + c][3] = f.w;
        }

        float h0[8][4];
        #pragma unroll
        for (int c = 0; c < 8; c++) {
            float b = Wp[152 + c];
            float a0 = b, a1 = b, a2 = b, a3 = b;
            #pragma unroll
            for (int i = 0; i < 10; i++) {
                float w = Wp[c * 10 + i];
                a0 = fmaf(w, v[i][0], a0);
                a1 = fmaf(w, v[i][1], a1);
                a2 = fmaf(w, v[i][2], a2);
                a3 = fmaf(w, v[i][3], a3);
            }
            h0[c][0] = fmaxf(a0, 0.f); h0[c][1] = fmaxf(a1, 0.f);
            h0[c][2] = fmaxf(a2, 0.f); h0[c][3] = fmaxf(a3, 0.f);
        }

        float h1[8][4];
        #pragma unroll
        for (int c = 0; c < 8; c++) {
            float b = Wp[160 + c];
            float a0 = b, a1 = b, a2 = b, a3 = b;
            #pragma unroll
            for (int i = 0; i < 8; i++) {
                float w = Wp[80 + c * 8 + i];
                a0 = fmaf(w, h0[i][0], a0);
                a1 = fmaf(w, h0[i][1], a1);
                a2 = fmaf(w, h0[i][2], a2);
                a3 = fmaf(w, h0[i][3], a3);
            }
            h1[c][0] = fmaxf(a0, 0.f); h1[c][1] = fmaxf(a1, 0.f);
            h1[c][2] = fmaxf(a2, 0.f); h1[c][3] = fmaxf(a3, 0.f);
        }

        float b2 = Wp[168];
        float z0 = b2, z1 = b2, z2 = b2, z3 = b2;
        #pragma unroll
        for (int i = 0; i < 8; i++) {
            float w = Wp[144 + i];
            z0 = fmaf(w, h1[i][0], z0);
            z1 = fmaf(w, h1[i][1], z1);
            z2 = fmaf(w, h1[i][2], z2);
            z3 = fmaf(w, h1[i][3], z3);
        }
        *reinterpret_cast<float4*>(Ls + p0) = make_float4(z0, z1, z2, z3);
    }
    __syncthreads();

    // ---- Phase C: aligned_bilinear(x2) + sigmoid + dice partials ----
    float inter = 0.f, ssum = 0.f, tsum = 0.f;
    const float* __restrict__ g = gt + (size_t)inst * OHW;

    for (int q0 = tid * 4; q0 < OHW; q0 += blockDim.x * 4) {
        int y  = q0 / OW;
        int x0 = q0 - y * OW;             // multiple of 4, same row for 4 px
        int k  = x0 >> 2;                 // chunk index; logit cols 2k-1..2k+1

        float4 t4 = *reinterpret_cast<const float4*>(g + q0);

        int jy  = max(y - 1, 0);
        int iy0 = jy >> 1;
        int iy1 = iy0 + (jy & 1);
        const float* r0 = Ls + iy0 * Ww;
        const float* r1 = Ls + iy1 * Ww;

        int cm = max(2 * k - 1, 0);
        int c0 = 2 * k;
        int cp = 2 * k + 1;

        // vertical blend (r1==r0 when even row => exact passthrough)
        float em = 0.5f * (r0[cm] + r1[cm]);
        float e0 = 0.5f * (r0[c0] + r1[c0]);
        float ep = 0.5f * (r0[cp] + r1[cp]);

        // horizontal: x=4k -> 0.5(em+e0) (k=0 clamps to e0), 4k+1 -> e0,
        //             4k+2 -> 0.5(e0+ep), 4k+3 -> ep
        float z0 = 0.5f * (em + e0);
        float z1 = e0;
        float z2 = 0.5f * (e0 + ep);
        float z3 = ep;

        float s0 = __fdividef(1.f, 1.f + __expf(-z0));
        float s1 = __fdividef(1.f, 1.f + __expf(-z1));
        float s2 = __fdividef(1.f, 1.f + __expf(-z2));
        float s3 = __fdividef(1.f, 1.f + __expf(-z3));

        inter = fmaf(s0, t4.x, inter); ssum = fmaf(s0, s0, ssum); tsum = fmaf(t4.x, t4.x, tsum);
        inter = fmaf(s1, t4.y, inter); ssum = fmaf(s1, s1, ssum); tsum = fmaf(t4.y, t4.y, tsum);
        inter = fmaf(s2, t4.z, inter); ssum = fmaf(s2, s2, ssum); tsum = fmaf(t4.z, t4.z, tsum);
        inter = fmaf(s3, t4.w, inter); ssum = fmaf(s3, s3, ssum); tsum = fmaf(t4.w, t4.w, tsum);
    }

    // ---- Phase D: block reduce 3 sums, per-instance dice, atomic mean ----
    #pragma unroll
    for (int off = 16; off > 0; off >>= 1) {
        inter += __shfl_down_sync(0xffffffffu, inter, off);
        ssum  += __shfl_down_sync(0xffffffffu, ssum,  off);
        tsum  += __shfl_down_sync(0xffffffffu, tsum,  off);
    }
    int warp = tid >> 5;
    if ((tid & 31) == 0) {
        red[warp]      = inter;
        red[8 + warp]  = ssum;
        red[16 + warp] = tsum;
    }
    __syncthreads();
    if (tid == 0) {
        float I = 0.f, S = 0.f, T = 0.f;
        #pragma unroll
        for (int w = 0; w < 8; w++) { I += red[w]; S += red[8 + w]; T += red[16 + w]; }
        float loss = 1.0f - 2.0f * I / (S + T + 1e-5f);
        atomicAdd(out, loss * inv_n);
    }
}

extern "C" void kernel_launch(void* const* d_in, const int* in_sizes, int n_in,
                              void* d_out, int out_size)
{
    const float* mask_feats = (const float*)d_in[0];
    const float* params     = (const float*)d_in[1];
    const float* locs       = (const float*)d_in[2];
    const float* gt         = (const float*)d_in[3];
    const int*   im_inds    = (const int*)d_in[4];
    const int*   fpn_levels = (const int*)d_in[5];
    float* out = (float*)d_out;

    int n_inst = in_sizes[1] / NPARAM;

    static int smem_set = 0;
    size_t smem_bytes = (HW + NPARAM + 7 + 24) * sizeof(float);
    if (!smem_set) {
        cudaFuncSetAttribute(dmh_kernel, cudaFuncAttributeMaxDynamicSharedMemorySize,
                             (int)smem_bytes);
        smem_set = 1;
    }

    dmh_zero<<<1, 1>>>(out);
    dmh_kernel<<<n_inst, 256, smem_bytes>>>(mask_feats, params, locs, gt,
                                            im_inds, fpn_levels, out,
                                            1.0f / (float)n_inst);
}

// round 3
// speedup vs baseline: 1.0161x; 1.0161x over previous
#include <cuda_runtime.h>
#include <cuda_bf16.h>

#define Hh 100
#define Ww 136
#define HW (Hh*Ww)      // 13600
#define OH 200
#define OW 272
#define OHW (OH*OW)     // 54400
#define NPARAM 169

typedef unsigned long long u64;

// ---- packed f32x2 helpers (sm_100+ PTX; ptxas will not auto-fuse these) ----
__device__ __forceinline__ u64 pack2(float a, float b) {
    u64 r; asm("mov.b64 %0, {%1, %2};" : "=l"(r) : "f"(a), "f"(b)); return r;
}
__device__ __forceinline__ void unpack2(u64 v, float& a, float& b) {
    asm("mov.b64 {%0, %1}, %2;" : "=f"(a), "=f"(b) : "l"(v));
}
__device__ __forceinline__ u64 fma2(u64 a, u64 b, u64 c) {
    u64 d; asm("fma.rn.f32x2 %0, %1, %2, %3;" : "=l"(d) : "l"(a), "l"(b), "l"(c)); return d;
}
__device__ __forceinline__ u64 relu2(u64 v) {
    float a, b; unpack2(v, a, b);
    return pack2(fmaxf(a, 0.f), fmaxf(b, 0.f));
}
__device__ __forceinline__ float sigm(float z) {
    float t; asm("tanh.approx.f32 %0, %1;" : "=f"(t) : "f"(z * 0.5f));
    return fmaf(t, 0.5f, 0.5f);
}

// params layout: w0[8][10]@0, w1[8][8]@80, w2[8]@144, b0[8]@152, b1[8]@160, b2@168

__global__ void dmh_zero(float* out) { out[0] = 0.0f; }

__global__ void __launch_bounds__(256)
dmh_kernel(const float* __restrict__ mask_feats,
           const float* __restrict__ params,
           const float* __restrict__ locs,
           const float* __restrict__ gt,
           const int*   __restrict__ im_inds,
           const int*   __restrict__ fpn_levels,
           float* __restrict__ out,
           float inv_n)
{
    extern __shared__ float smem[];
    float* Ls  = smem;                          // HW logits (54400 f, 8B-aligned end)
    u64*   Wd  = (u64*)(smem + HW);             // 169 duplicated params {w,w}
    float* red = (float*)(Wd + NPARAM + 1);     // 24 floats reduction scratch

    const int inst = blockIdx.x;
    const int tid  = threadIdx.x;

    // ---- Phase A: load per-instance params, duplicated for packed math ----
    for (int i = tid; i < NPARAM; i += blockDim.x) {
        float w = params[inst * NPARAM + i];
        Wd[i] = pack2(w, w);
    }

    const int im  = im_inds[inst];
    const int lvl = fpn_levels[inst];
    const float soi_tab[5] = {8.f, 16.f, 32.f, 64.f, 128.f};
    const float inv_soi = 1.0f / soi_tab[lvl];
    const float lx = locs[inst * 2 + 0];
    const float ly = locs[inst * 2 + 1];
    const float* __restrict__ feat = mask_feats + (size_t)im * 8 * HW;
    __syncthreads();

    // ---- Phase B: per-pixel 3-layer MLP with packed f32x2 FMA ----
    // 4 consecutive pixels/thread = 2 packed lanes. Ww=136 is divisible by 4,
    // so a quad never crosses a row.
    for (int p0 = tid * 4; p0 < HW; p0 += blockDim.x * 4) {
        int y = p0 / Ww;
        int x = p0 - y * Ww;
        float cy  = (ly - (float)(y * 8 + 4)) * inv_soi;
        float cx0 = (lx - (float)(x * 8 + 4)) * inv_soi;
        float dx  = -8.f * inv_soi;

        u64 v2[10][2];
        v2[0][0] = pack2(cx0, cx0 + dx);
        v2[0][1] = pack2(cx0 + 2.f * dx, cx0 + 3.f * dx);
        v2[1][0] = pack2(cy, cy);
        v2[1][1] = v2[1][0];
        #pragma unroll
        for (int c = 0; c < 8; c++) {
            float4 f = *reinterpret_cast<const float4*>(feat + c * HW + p0);
            v2[2 + c][0] = pack2(f.x, f.y);
            v2[2 + c][1] = pack2(f.z, f.w);
        }

        u64 h0[8][2];
        #pragma unroll
        for (int c = 0; c < 8; c++) {
            u64 b  = Wd[152 + c];
            u64 a0 = b, a1 = b;
            #pragma unroll
            for (int i = 0; i < 10; i++) {
                u64 w = Wd[c * 10 + i];
                a0 = fma2(w, v2[i][0], a0);
                a1 = fma2(w, v2[i][1], a1);
            }
            h0[c][0] = relu2(a0);
            h0[c][1] = relu2(a1);
        }

        u64 h1[8][2];
        #pragma unroll
        for (int c = 0; c < 8; c++) {
            u64 b  = Wd[160 + c];
            u64 a0 = b, a1 = b;
            #pragma unroll
            for (int i = 0; i < 8; i++) {
                u64 w = Wd[80 + c * 8 + i];
                a0 = fma2(w, h0[i][0], a0);
                a1 = fma2(w, h0[i][1], a1);
            }
            h1[c][0] = relu2(a0);
            h1[c][1] = relu2(a1);
        }

        u64 zb = Wd[168];
        u64 z0 = zb, z1 = zb;
        #pragma unroll
        for (int i = 0; i < 8; i++) {
            u64 w = Wd[144 + i];
            z0 = fma2(w, h1[i][0], z0);
            z1 = fma2(w, h1[i][1], z1);
        }
        float o0, o1, o2, o3;
        unpack2(z0, o0, o1);
        unpack2(z1, o2, o3);
        *reinterpret_cast<float4*>(Ls + p0) = make_float4(o0, o1, o2, o3);
    }
    __syncthreads();

    // ---- Phase C: aligned_bilinear(x2) + sigmoid + dice partials ----
    float inter = 0.f, ssum = 0.f, tsum = 0.f;
    const float* __restrict__ g = gt + (size_t)inst * OHW;

    for (int q0 = tid * 4; q0 < OHW; q0 += blockDim.x * 4) {
        int y  = q0 / OW;
        int x0 = q0 - y * OW;             // multiple of 4, same row for 4 px
        int k  = x0 >> 2;                 // logit cols 2k-1..2k+1

        float4 t4 = *reinterpret_cast<const float4*>(g + q0);

        int jy  = max(y - 1, 0);
        int iy0 = jy >> 1;
        int iy1 = iy0 + (jy & 1);
        const float* r0 = Ls + iy0 * Ww;
        const float* r1 = Ls + iy1 * Ww;

        int cm = max(2 * k - 1, 0);
        int c0 = 2 * k;

        // even column pair is 8B-aligned -> LDS.64
        float2 a0 = *reinterpret_cast<const float2*>(r0 + c0);
        float2 a1 = *reinterpret_cast<const float2*>(r1 + c0);
        float  m0 = r0[cm];
        float  m1 = r1[cm];

        // vertical blend (r1==r0 on even rows => exact passthrough)
        float em = 0.5f * (m0 + m1);
        float e0 = 0.5f * (a0.x + a1.x);
        float ep = 0.5f * (a0.y + a1.y);

        // horizontal: x=4k -> 0.5(em+e0) (k=0 clamps to e0), 4k+1 -> e0,
        //             4k+2 -> 0.5(e0+ep), 4k+3 -> ep
        float z0 = 0.5f * (em + e0);
        float z1 = e0;
        float z2 = 0.5f * (e0 + ep);
        float z3 = ep;

        float s0 = sigm(z0);
        float s1 = sigm(z1);
        float s2 = sigm(z2);
        float s3 = sigm(z3);

        inter = fmaf(s0, t4.x, inter); ssum = fmaf(s0, s0, ssum); tsum = fmaf(t4.x, t4.x, tsum);
        inter = fmaf(s1, t4.y, inter); ssum = fmaf(s1, s1, ssum); tsum = fmaf(t4.y, t4.y, tsum);
        inter = fmaf(s2, t4.z, inter); ssum = fmaf(s2, s2, ssum); tsum = fmaf(t4.z, t4.z, tsum);
        inter = fmaf(s3, t4.w, inter); ssum = fmaf(s3, s3, ssum); tsum = fmaf(t4.w, t4.w, tsum);
    }

    // ---- Phase D: block reduce 3 sums, per-instance dice, atomic mean ----
    #pragma unroll
    for (int off = 16; off > 0; off >>= 1) {
        inter += __shfl_down_sync(0xffffffffu, inter, off);
        ssum  += __shfl_down_sync(0xffffffffu, ssum,  off);
        tsum  += __shfl_down_sync(0xffffffffu, tsum,  off);
    }
    int warp = tid >> 5;
    if ((tid & 31) == 0) {
        red[warp]      = inter;
        red[8 + warp]  = ssum;
        red[16 + warp] = tsum;
    }
    __syncthreads();
    if (tid == 0) {
        float I = 0.f, S = 0.f, T = 0.f;
        #pragma unroll
        for (int w = 0; w < 8; w++) { I += red[w]; S += red[8 + w]; T += red[16 + w]; }
        float loss = 1.0f - 2.0f * I / (S + T + 1e-5f);
        atomicAdd(out, loss * inv_n);
    }
}

extern "C" void kernel_launch(void* const* d_in, const int* in_sizes, int n_in,
                              void* d_out, int out_size)
{
    const float* mask_feats = (const float*)d_in[0];
    const float* params     = (const float*)d_in[1];
    const float* locs       = (const float*)d_in[2];
    const float* gt         = (const float*)d_in[3];
    const int*   im_inds    = (const int*)d_in[4];
    const int*   fpn_levels = (const int*)d_in[5];
    float* out = (float*)d_out;

    int n_inst = in_sizes[1] / NPARAM;

    static int smem_set = 0;
    size_t smem_bytes = HW * sizeof(float) + (NPARAM + 1) * sizeof(u64) + 32 * sizeof(float);
    if (!smem_set) {
        cudaFuncSetAttribute(dmh_kernel, cudaFuncAttributeMaxDynamicSharedMemorySize,
                             (int)smem_bytes);
        smem_set = 1;
    }

    dmh_zero<<<1, 1>>>(out);
    dmh_kernel<<<n_inst, 256, smem_bytes>>>(mask_feats, params, locs, gt,
                                            im_inds, fpn_levels, out,
                                            1.0f / (float)n_inst);
}